// round 3
// baseline (speedup 1.0000x reference)
#include <cuda_runtime.h>

// CRF loss + Viterbi decode. B=256, T=1024, K=64. mask all-ones.
// Output (float32, 262146): [0]=loss, [1..B*T]=decoded, [1+B*T]=tag_accuracy.
//
// One block per batch, 128 threads: thread tid -> state j=tid>>1, half h=tid&1
// owns predecessor range [32h,32h+32). No in-loop argmax: Viterbi max values
// stored to global; backpointers recovered exactly during a warp-pipelined
// backtrack via equality ballot against the stored max.

#define BB 256
#define TT 1024
#define KK 64
#define NTH 128
#define DPF 4

__device__ float g_ll[BB];
__device__ int   g_corr[BB];
__device__ float g_best[BB][TT-1][KK];   // best_t[j] (pre-emission max), t=1..1023
__device__ int   g_count;                // zero-init; reset by last block

static __device__ __forceinline__ void ffma2(unsigned long long &acc,
                                             unsigned long long a, unsigned long long b) {
    asm("fma.rn.f32x2 %0,%1,%2,%0;" : "+l"(acc) : "l"(a), "l"(b));
}
static __device__ __forceinline__ unsigned long long pk2(float lo, float hi) {
    unsigned long long r; asm("mov.b64 %0,{%1,%2};" : "=l"(r) : "f"(lo), "f"(hi)); return r;
}
static __device__ __forceinline__ void upk2(unsigned long long v, float &lo, float &hi) {
    asm("mov.b64 {%0,%1},%2;" : "=f"(lo), "=f"(hi) : "l"(v));
}

__global__ void __launch_bounds__(NTH) crf_main(
    const float* __restrict__ em,      // [B,T,K]
    const int*   __restrict__ tags,    // [B,T]
    const float* __restrict__ trans,   // [K,K]
    float*       __restrict__ out)
{
    __shared__ __align__(16) float s_w[2*KK];
    __shared__ __align__(16) float s_delta[2*KK];
    __shared__ float s_m[2];
    __shared__ float s_redf[4];
    __shared__ int   s_dec[TT];
    __shared__ float s_trT[KK*KK];     // s_trT[j*64+i] = trans[i][j]
    __shared__ int   s_last;

    const int tid = threadIdx.x;
    const int b   = blockIdx.x;
    const int j   = tid >> 1;
    const int h   = tid & 1;
    const int base_i = h << 5;

    const float* e_b   = em   + (size_t)b * TT * KK;
    const int*   tag_b = tags + b * TT;
    const float* gb    = &g_best[b][0][0];

    // trans column j (rows base_i..+31): tr for viterbi, exp(tr) packed for forward
    float tr[32];
    unsigned long long exq[16];
#pragma unroll
    for (int i = 0; i < 32; i++) tr[i] = trans[(base_i + i)*KK + j];
#pragma unroll
    for (int k = 0; k < 16; k++) exq[k] = pk2(__expf(tr[2*k]), __expf(tr[2*k + 1]));

    // transposed trans into smem (for backtrack column reads)
    for (int idx = tid; idx < KK*KK; idx += NTH)
        s_trT[(idx & 63)*KK + (idx >> 6)] = trans[idx];

    // ---- sequence score gathers ----
    {
        float ss = 0.f;
        for (int t = tid; t < TT; t += NTH) {
            int tg = tag_b[t];
            ss += e_b[t*KK + tg];
            if (t > 0) ss += trans[tag_b[t-1]*KK + tg];
        }
#pragma unroll
        for (int o = 16; o > 0; o >>= 1) ss += __shfl_down_sync(0xffffffffu, ss, o);
        if ((tid & 31) == 0) s_redf[tid >> 5] = ss;
    }

    // ---- init t=0 ----
    float a0  = e_b[j];
    float a00 = e_b[0];
    if (h == 0) {
        s_w[j]     = __expf(a0 - a00);
        s_delta[j] = a0;
    }
    if (tid == 0) s_m[0] = a00;
    float mA = a00;

    float e_cur = e_b[KK + j];
    float e_nx  = e_b[2*KK + j];
    __syncthreads();

    // ---- main recurrence (no argmax) ----
    for (int t = 1; t < TT; t++) {
        int pidx = (t + 2 < TT) ? (t + 2) : (TT - 1);
        float e_f = e_b[pidx*KK + j];

        float mB = s_m[(t - 1) & 1];
        const double* wb = (const double*)(s_w     + ((t - 1) & 1)*KK + base_i);
        const float4* db = (const float4*)(s_delta + ((t - 1) & 1)*KK + base_i);

        unsigned long long acc0 = 0ull, acc1 = 0ull;
        float bloc;
#pragma unroll
        for (int q = 0; q < 8; q++) {
            unsigned long long wA = __double_as_longlong(wb[2*q]);
            unsigned long long wB = __double_as_longlong(wb[2*q + 1]);
            ffma2(acc0, wA, exq[2*q]);
            ffma2(acc1, wB, exq[2*q + 1]);
            float4 d4 = db[q];
            float s0 = d4.x + tr[4*q + 0];
            float s1 = d4.y + tr[4*q + 1];
            float s2 = d4.z + tr[4*q + 2];
            float s3 = d4.w + tr[4*q + 3];
            float m01 = fmaxf(s0, s1);
            float m23 = fmaxf(s2, s3);
            float mq  = fmaxf(m01, m23);
            bloc = (q == 0) ? mq : fmaxf(bloc, mq);
        }
        float x0, x1, x2, x3;
        upk2(acc0, x0, x1); upk2(acc1, x2, x3);
        float up = (x0 + x1) + (x2 + x3);

        float ou  = __shfl_xor_sync(0xffffffffu, up,   1);
        float ob  = __shfl_xor_sync(0xffffffffu, bloc, 1);
        float u    = up + ou;
        float best = fmaxf(bloc, ob);

        float a_new = mA + __logf(u) + e_cur;
        float d_new = best + e_cur;

        if (h == 0) {
            s_delta[(t & 1)*KK + j] = d_new;
            g_best[b][t - 1][j] = best;           // pre-emission max, exact
        } else {
            s_w[(t & 1)*KK + j] = __expf(a_new - mB);
        }
        if (tid == 0) s_m[t & 1] = a_new;

        mA = mB;
        e_cur = e_nx;
        e_nx  = e_f;
        __syncthreads();
    }

    // ---- epilogue: warp0 = backtrack (exact recompute), warp1 = log_z ----
    const int wid = tid >> 5;
    if (wid == 0) {
        const int l = tid;      // 0..31; lane l covers states l, l+32
        // last-tag argmax from delta_{1023} (smem slot 1), exact first-index
        float dlo = s_delta[KK + l];
        float dhi = s_delta[KK + 32 + l];
        float mx = fmaxf(dlo, dhi);
#pragma unroll
        for (int o = 16; o > 0; o >>= 1) mx = fmaxf(mx, __shfl_xor_sync(0xffffffffu, mx, o));
        unsigned bl0 = __ballot_sync(0xffffffffu, dlo == mx);
        unsigned bh0 = __ballot_sync(0xffffffffu, dhi == mx);
        int cur = bl0 ? (__ffs(bl0) - 1) : (__ffs(bh0) + 31);
        if (l == 0) s_dec[TT - 1] = cur;

        // prefetch ring: A(t)=g_best row t-1, E(t)=em row t-1
        float A_lo[DPF], A_hi[DPF], E_lo[DPF], E_hi[DPF];
#pragma unroll
        for (int k = 0; k < DPF; k++) {
            const int t = TT - 1 - k;            // 1023..1020 (compile-time)
            const int d = t & (DPF - 1);
            A_lo[d] = gb[(t - 1)*KK + l];
            A_hi[d] = gb[(t - 1)*KK + 32 + l];
            E_lo[d] = e_b[(t - 1)*KK + l];
            E_hi[d] = e_b[(t - 1)*KK + 32 + l];
        }

#define BSTEP(T_, D_, D1_) {                                                    \
        float tl = __shfl_sync(0xffffffffu, A_lo[D_], cur & 31);                \
        float th = __shfl_sync(0xffffffffu, A_hi[D_], cur & 31);                \
        float target = (cur < 32) ? tl : th;                                    \
        float dl = E_lo[D_], dh = E_hi[D_];                                     \
        if ((T_) >= 2) { dl += A_lo[D1_]; dh += A_hi[D1_]; }                    \
        float sl = dl + s_trT[cur*KK + l];                                      \
        float sh = dh + s_trT[cur*KK + 32 + l];                                 \
        unsigned mbl = __ballot_sync(0xffffffffu, sl == target);                \
        unsigned mbh = __ballot_sync(0xffffffffu, sh == target);                \
        cur = mbl ? (__ffs(mbl) - 1) : (__ffs(mbh) + 31);                       \
        if (l == 0) s_dec[(T_) - 1] = cur;                                      \
        int tp = (T_) - DPF;                                                    \
        if (tp >= 1) {                                                          \
            A_lo[D_] = gb[(tp - 1)*KK + l];                                     \
            A_hi[D_] = gb[(tp - 1)*KK + 32 + l];                                \
            E_lo[D_] = e_b[(tp - 1)*KK + l];                                    \
            E_hi[D_] = e_b[(tp - 1)*KK + 32 + l];                               \
        } }

        int t = TT - 1;                           // 1023 (== 3 mod 4)
        for (; t >= 4; t -= 4) {
            BSTEP(t,     3, 2);
            BSTEP(t - 1, 2, 1);
            BSTEP(t - 2, 1, 0);
            BSTEP(t - 3, 0, 3);
        }
        BSTEP(3, 3, 2);
        BSTEP(2, 2, 1);
        BSTEP(1, 1, 0);
#undef BSTEP
    } else if (wid == 1) {
        const int l = tid - 32;
        float wv = s_w[KK + l] + s_w[KK + 32 + l];    // slot 1 = w_{1023}
#pragma unroll
        for (int o = 16; o > 0; o >>= 1) wv += __shfl_xor_sync(0xffffffffu, wv, o);
        if (l == 0) {
            float log_z = mA + __logf(wv);
            float seq = (s_redf[0] + s_redf[1]) + (s_redf[2] + s_redf[3]);
            g_ll[b] = seq - log_z;
        }
    }
    __syncthreads();

    // ---- write decoded + count matches ----
    int corr = 0;
    float* o_dec = out + 1 + (size_t)b * TT;
    for (int t = tid; t < TT; t += NTH) {
        int d = s_dec[t];
        o_dec[t] = (float)d;
        corr += (d == tag_b[t]) ? 1 : 0;
    }
#pragma unroll
    for (int o = 16; o > 0; o >>= 1) corr += __shfl_down_sync(0xffffffffu, corr, o);
    if ((tid & 31) == 0) ((int*)s_redf)[tid >> 5] = corr;
    __syncthreads();
    if (tid == 0) {
        int* ri = (int*)s_redf;
        g_corr[b] = (ri[0] + ri[1]) + (ri[2] + ri[3]);
        __threadfence();
        int old = atomicAdd(&g_count, 1);
        s_last = (old == BB - 1) ? 1 : 0;
    }
    __syncthreads();

    // ---- last block reduces loss + accuracy ----
    if (s_last) {
        __threadfence();
        float sum = 0.f; int cs = 0;
        for (int i = tid; i < BB; i += NTH) { sum += g_ll[i]; cs += g_corr[i]; }
#pragma unroll
        for (int o = 16; o > 0; o >>= 1) {
            sum += __shfl_down_sync(0xffffffffu, sum, o);
            cs  += __shfl_down_sync(0xffffffffu, cs,  o);
        }
        __shared__ float rf[4];
        __shared__ int   rc[4];
        if ((tid & 31) == 0) { rf[tid >> 5] = sum; rc[tid >> 5] = cs; }
        __syncthreads();
        if (tid == 0) {
            float ts = (rf[0] + rf[1]) + (rf[2] + rf[3]);
            int   tc = (rc[0] + rc[1]) + (rc[2] + rc[3]);
            out[0]         = -(ts / (float)BB);
            out[1 + BB*TT] = (float)tc / (float)(BB*TT);
            g_count = 0;                 // reset for next replay
        }
    }
}

extern "C" void kernel_launch(void* const* d_in, const int* in_sizes, int n_in,
                              void* d_out, int out_size)
{
    const float* em    = (const float*)d_in[0];   // emissions [256,1024,64] f32
    const int*   tags  = (const int*)  d_in[1];   // tag_ids   [256,1024]    i32
    // d_in[2] = mask (all true) — unused
    const float* trans = (const float*)d_in[3];   // transition_weight [64,64] f32
    float* out = (float*)d_out;

    crf_main<<<BB, NTH>>>(em, tags, trans, out);
}

// round 4
// speedup vs baseline: 1.3664x; 1.3664x over previous
#include <cuda_runtime.h>

// CRF loss + Viterbi decode. B=256, T=1024, K=64. mask all-ones.
// Output (float32, 262146): [0]=loss, [1..B*T]=decoded, [1+B*T]=tag_accuracy.
//
// 128 threads/block, block b = batch b. Thread tid: state j=tid>>1, half h=tid&1
// owns predecessor range [32h, 32h+32). Lane pairs merge via shfl.
// Emissions prefetched 8 steps ahead in a register ring; w-update is log-free
// on the critical path (w = u * exp((mA-mB)+e), argument known at step start).

#define BB 256
#define TT 1024
#define KK 64
#define NTH 128

__device__ float g_ll[BB];
__device__ int   g_corr[BB];

// smem floats: w[2*64] | delta[2*64] | m[2] | redf[4], then int dec[1024], uchar bp[1023*64]
#define SMEM_F (128 + 128 + 2 + 4)
#define SMEM_BYTES (SMEM_F*4 + TT*4 + (TT-1)*KK)

static __device__ __forceinline__ unsigned long long pk2(float lo, float hi) {
    unsigned long long r; asm("mov.b64 %0,{%1,%2};" : "=l"(r) : "f"(lo), "f"(hi)); return r;
}
static __device__ __forceinline__ void upk2(unsigned long long v, float &lo, float &hi) {
    asm("mov.b64 {%0,%1},%2;" : "=f"(lo), "=f"(hi) : "l"(v));
}
static __device__ __forceinline__ void ffma2(unsigned long long &acc,
                                             unsigned long long a, unsigned long long b) {
    asm("fma.rn.f32x2 %0,%1,%2,%0;" : "+l"(acc) : "l"(a), "l"(b));
}

__global__ void __launch_bounds__(NTH) crf_main(
    const float* __restrict__ em,      // [B,T,K]
    const int*   __restrict__ tags,    // [B,T]
    const float* __restrict__ trans,   // [K,K]
    float*       __restrict__ out)
{
    extern __shared__ char smem[];
    float* s_w     = (float*)smem;                  // 2*64 double buffer
    float* s_delta = s_w + 2*KK;                    // 2*64 double buffer
    float* s_m     = s_delta + 2*KK;                // 2 ping-pong scale
    float* s_redf  = s_m + 2;                       // 4 warp partials
    int*   s_dec   = (int*)(smem + SMEM_F*4);       // 1024
    unsigned char* s_bp = (unsigned char*)(s_dec + TT); // 1023*64

    const int tid = threadIdx.x;
    const int b   = blockIdx.x;
    const int j   = tid >> 1;
    const int h   = tid & 1;
    const int base_i = h << 5;

    const float* e_b   = em   + (size_t)b * TT * KK;
    const int*   tag_b = tags + b * TT;

    // Half-column of trans (rows base_i..+31, col j): tr for viterbi, exp(tr) packed.
    float tr[32];
    unsigned long long exq[16];
#pragma unroll
    for (int i = 0; i < 32; i++) tr[i] = trans[(base_i + i)*KK + j];
#pragma unroll
    for (int k = 0; k < 16; k++) exq[k] = pk2(__expf(tr[2*k]), __expf(tr[2*k + 1]));

    // ---- sequence score gathers ----
    {
        float ss = 0.f;
        for (int t = tid; t < TT; t += NTH) {
            int tg = tag_b[t];
            ss += e_b[t*KK + tg];
            if (t > 0) ss += trans[tag_b[t-1]*KK + tg];
        }
#pragma unroll
        for (int o = 16; o > 0; o >>= 1) ss += __shfl_down_sync(0xffffffffu, ss, o);
        if ((tid & 31) == 0) s_redf[tid >> 5] = ss;
    }

    // ---- init t=0 ----
    float a0  = e_b[j];
    float a00 = e_b[0];
    if (h == 0) {
        s_w[j]     = __expf(a0 - a00);
        s_delta[j] = a0;
    }
    if (tid == 0) s_m[0] = a00;
    float mA = a00;                       // scale of w currently in active slot

    // emission prefetch ring: E[k] = e(tb + k, j)
    float E[8];
#pragma unroll
    for (int k = 0; k < 8; k++) E[k] = e_b[(1 + k)*KK + j];
    __syncthreads();

#define STEP(T_, ECUR_) {                                                       \
        const int t_ = (T_);                                                    \
        float mB = s_m[(t_ - 1) & 1];                                           \
        float p  = __expf((mA - mB) + (ECUR_));      /* off critical path */    \
        const double* wb = (const double*)(s_w     + ((t_ - 1) & 1)*KK + base_i);\
        const float4* db = (const float4*)(s_delta + ((t_ - 1) & 1)*KK + base_i);\
        unsigned long long pa[4] = {0ull, 0ull, 0ull, 0ull};                    \
        float cb[4]; int ca[4];                                                 \
        _Pragma("unroll")                                                       \
        for (int q = 0; q < 8; q++) {                                           \
            ffma2(pa[(2*q) & 3],     __double_as_longlong(wb[2*q]),     exq[2*q]);     \
            ffma2(pa[(2*q + 1) & 3], __double_as_longlong(wb[2*q + 1]), exq[2*q + 1]); \
            float4 d4 = db[q];                                                  \
            const int c = q >> 1;                                               \
            float s0 = d4.x + tr[4*q + 0];                                      \
            float s1 = d4.y + tr[4*q + 1];                                      \
            float s2 = d4.z + tr[4*q + 2];                                      \
            float s3 = d4.w + tr[4*q + 3];                                      \
            if ((q & 1) == 0) { cb[c] = s0; ca[c] = 4*q; }                      \
            else { bool g0 = s0 > cb[c]; cb[c] = fmaxf(cb[c], s0); ca[c] = g0 ? 4*q     : ca[c]; } \
            {      bool g1 = s1 > cb[c]; cb[c] = fmaxf(cb[c], s1); ca[c] = g1 ? 4*q + 1 : ca[c]; } \
            {      bool g2 = s2 > cb[c]; cb[c] = fmaxf(cb[c], s2); ca[c] = g2 ? 4*q + 2 : ca[c]; } \
            {      bool g3 = s3 > cb[c]; cb[c] = fmaxf(cb[c], s3); ca[c] = g3 ? 4*q + 3 : ca[c]; } \
        }                                                                       \
        {                                                                       \
            bool g;                                                             \
            g = cb[1] > cb[0]; cb[0] = g ? cb[1] : cb[0]; ca[0] = g ? ca[1] : ca[0]; \
            g = cb[3] > cb[2]; cb[2] = g ? cb[3] : cb[2]; ca[2] = g ? ca[3] : ca[2]; \
            g = cb[2] > cb[0]; cb[0] = g ? cb[2] : cb[0]; ca[0] = g ? ca[2] : ca[0]; \
        }                                                                       \
        float bestl = cb[0];                                                    \
        int   argl  = ca[0] + base_i;                                           \
        float x0, x1, x2, x3, x4, x5, x6, x7;                                   \
        upk2(pa[0], x0, x1); upk2(pa[1], x2, x3);                               \
        upk2(pa[2], x4, x5); upk2(pa[3], x6, x7);                               \
        float up = ((x0 + x1) + (x2 + x3)) + ((x4 + x5) + (x6 + x7));           \
        float ou  = __shfl_xor_sync(0xffffffffu, up, 1);                        \
        float obb = __shfl_xor_sync(0xffffffffu, bestl, 1);                     \
        int   oaa = __shfl_xor_sync(0xffffffffu, argl, 1);                      \
        float u = up + ou;                                                      \
        float lob = h ? obb : bestl;  int loa = h ? oaa : argl;                 \
        float hib = h ? bestl : obb;  int hia = h ? argl : oaa;                 \
        bool  gg  = hib > lob;                                                  \
        float best = gg ? hib : lob;                                            \
        int   arg  = gg ? hia : loa;                                            \
        float d_new = best + (ECUR_);                                           \
        if (h == 0) {                                                           \
            s_bp[(t_ - 1)*KK + j]    = (unsigned char)arg;                      \
            s_delta[(t_ & 1)*KK + j] = d_new;                                   \
        } else {                                                                \
            s_w[(t_ & 1)*KK + j] = u * p;                                       \
        }                                                                       \
        if (tid == 0) s_m[t_ & 1] = mA + __logf(u) + (ECUR_);                   \
        mA = mB;                                                                \
        __syncthreads();                                                        \
    }

    // ---- main recurrence: t = 1..1016 unrolled by 8, ring prefetch 8 ahead ----
    for (int tb = 1; tb + 8 <= TT; tb += 8) {
#pragma unroll
        for (int k = 0; k < 8; k++) {
            const int t = tb + k;
            float e_cur = E[k];
            if (t + 8 < TT) E[k] = e_b[(t + 8)*KK + j];
            STEP(t, e_cur);
        }
    }
    // tail t = 1017..1023 (E[0..6] prefilled by last main iteration)
#pragma unroll
    for (int k = 0; k < 7; k++) {
        STEP(1017 + k, E[k]);
    }
#undef STEP

    // ---- epilogue (thread 0): log_z, final argmax, backtrack in SMEM ----
    if (tid == 0) {
        const float* wf = s_w + ((TT - 1) & 1)*KK;
        float sum = 0.f;
        for (int i = 0; i < KK; i++) sum += wf[i];
        float log_z = mA + __logf(sum);
        float seq = (s_redf[0] + s_redf[1]) + (s_redf[2] + s_redf[3]);
        g_ll[b] = seq - log_z;

        const float* df = s_delta + ((TT - 1) & 1)*KK;
        float bd = df[0]; int cur = 0;
        for (int i = 1; i < KK; i++) { float v = df[i]; if (v > bd) { bd = v; cur = i; } }
        s_dec[TT - 1] = cur;
        for (int t = TT - 1; t >= 1; t--) {
            cur = s_bp[(t - 1)*KK + cur];
            s_dec[t - 1] = cur;
        }
    }
    __syncthreads();

    // ---- write decoded (as float) + count matches ----
    int corr = 0;
    float* o_dec = out + 1 + (size_t)b * TT;
    for (int t = tid; t < TT; t += NTH) {
        int d = s_dec[t];
        o_dec[t] = (float)d;
        corr += (d == tag_b[t]) ? 1 : 0;
    }
#pragma unroll
    for (int o = 16; o > 0; o >>= 1) corr += __shfl_down_sync(0xffffffffu, corr, o);
    if ((tid & 31) == 0) ((int*)s_redf)[tid >> 5] = corr;
    __syncthreads();
    if (tid == 0) {
        int* ri = (int*)s_redf;
        g_corr[b] = (ri[0] + ri[1]) + (ri[2] + ri[3]);
    }
}

__global__ void crf_finish(float* __restrict__ out)
{
    __shared__ float sf[BB];
    __shared__ int   si[BB];
    int t = threadIdx.x;
    sf[t] = g_ll[t];
    si[t] = g_corr[t];
    __syncthreads();
#pragma unroll
    for (int o = 128; o > 0; o >>= 1) {
        if (t < o) { sf[t] += sf[t + o]; si[t] += si[t + o]; }
        __syncthreads();
    }
    if (t == 0) {
        out[0]         = -(sf[0] / (float)BB);
        out[1 + BB*TT] = (float)si[0] / (float)(BB*TT);
    }
}

extern "C" void kernel_launch(void* const* d_in, const int* in_sizes, int n_in,
                              void* d_out, int out_size)
{
    const float* em    = (const float*)d_in[0];   // emissions [256,1024,64] f32
    const int*   tags  = (const int*)  d_in[1];   // tag_ids   [256,1024]    i32
    // d_in[2] = mask (all true) — unused
    const float* trans = (const float*)d_in[3];   // transition_weight [64,64] f32
    float* out = (float*)d_out;

    cudaFuncSetAttribute(crf_main, cudaFuncAttributeMaxDynamicSharedMemorySize, SMEM_BYTES);
    crf_main<<<BB, NTH, SMEM_BYTES>>>(em, tags, trans, out);
    crf_finish<<<1, BB>>>(out);
}